// round 1
// baseline (speedup 1.0000x reference)
#include <cuda_runtime.h>
#include <math.h>

#define NXc 32
#define NYc 32
#define NZc 32
#define NBc 16
#define LMEMc 64
#define MIDc 128
#define NROWS (NXc * NYc * NZc * NBc)   // 524288
#define TILE_R 32
#define THREADS 512

// scratch for x_nn (no cudaMalloc allowed)
__device__ float g_xnn[NROWS];

struct Smem {
    // weights, l-major packed: Wx4[l4*128 + m] = {W[m][4*l4 .. 4*l4+3]}
    float4 W1s4[16 * 128];    // 32 KB
    float4 W2s4[32 * 128];    // 64 KB
    float4 W1ns4[16 * 128];   // 32 KB
    float4 W2ns4[32 * 128];   // 64 KB
    float4 wts4[16];          // weight vector
    float4 ags4[16];          // ag_os_long vector
    float4 xws4[TILE_R * 16]; // x_w tile (32 rows x 64)
    float  W3s[128];
    float  W3ns[128];
    float  b1s[128], b2s[128], b1ns[128], b2ns[128];
    float  H[TILE_R * 128];   // hidden tile
    float  ars[TILE_R];       // AR dot per row
};

__global__ __launch_bounds__(THREADS, 1)
void mlp_kernel(const float* __restrict__ x_in, const float* __restrict__ weight,
                const float* __restrict__ ag,
                const float* __restrict__ W1, const float* __restrict__ b1,
                const float* __restrict__ W2, const float* __restrict__ b2,
                const float* __restrict__ W3, const float* __restrict__ b3,
                const float* __restrict__ W1n, const float* __restrict__ b1n,
                const float* __restrict__ W2n, const float* __restrict__ b2n,
                const float* __restrict__ W3n, const float* __restrict__ b3n,
                const float* __restrict__ max_os_l,
                float* __restrict__ out_os)
{
    extern __shared__ char smem_raw[];
    Smem& s = *reinterpret_cast<Smem*>(smem_raw);
    const int tid = threadIdx.x;
    const int m = tid & 127;
    const int g = tid >> 7;      // 0..3, owns rows g*8 .. g*8+7 of the tile

    // ---- load weights once per CTA (transposed to l-major) ----
    for (int q = tid; q < 128 * 16; q += THREADS) {
        int mm = q >> 4, l4 = q & 15;
        s.W1s4 [l4 * 128 + mm] = reinterpret_cast<const float4*>(W1 )[q];
        s.W1ns4[l4 * 128 + mm] = reinterpret_cast<const float4*>(W1n)[q];
    }
    for (int q = tid; q < 128 * 32; q += THREADS) {
        int mm = q >> 5, l4 = q & 31;
        s.W2s4 [l4 * 128 + mm] = reinterpret_cast<const float4*>(W2 )[q];
        s.W2ns4[l4 * 128 + mm] = reinterpret_cast<const float4*>(W2n)[q];
    }
    if (tid < 128) {
        s.W3s[tid]  = W3[tid];  s.W3ns[tid] = W3n[tid];
        s.b1s[tid]  = b1[tid];  s.b2s[tid]  = b2[tid];
        s.b1ns[tid] = b1n[tid]; s.b2ns[tid] = b2n[tid];
    }
    if (tid < 16) {
        s.wts4[tid] = reinterpret_cast<const float4*>(weight)[tid];
        s.ags4[tid] = reinterpret_cast<const float4*>(ag)[tid];
    }
    const float max_os = expf(max_os_l[0]);
    const float b3v  = b3[0];
    const float b3nv = b3n[0];
    __syncthreads();

    const int ntiles = NROWS / TILE_R;
    for (int tile = blockIdx.x; tile < ntiles; tile += gridDim.x) {
        const int row0 = tile * TILE_R;

        // ---- load x tile: compute x_w into smem + AR dot per row ----
        {
            int r = tid >> 4, l4 = tid & 15;
            float4 x4 = reinterpret_cast<const float4*>(x_in)[(row0 + r) * 16 + l4];
            float4 w4 = s.wts4[l4];
            float4 a4 = s.ags4[l4];
            s.xws4[r * 16 + l4] = make_float4(x4.x * w4.x, x4.y * w4.y,
                                              x4.z * w4.z, x4.w * w4.w);
            float arp = x4.x * a4.x + x4.y * a4.y + x4.z * a4.z + x4.w * a4.w;
            arp += __shfl_down_sync(0xffffffffu, arp, 8, 16);
            arp += __shfl_down_sync(0xffffffffu, arp, 4, 16);
            arp += __shfl_down_sync(0xffffffffu, arp, 2, 16);
            arp += __shfl_down_sync(0xffffffffu, arp, 1, 16);
            if (l4 == 0) s.ars[r] = arp;
        }
        __syncthreads();

        // ---- two MLP passes: which=0 -> onsite (out_os), which=1 -> nn (g_xnn) ----
        for (int which = 0; which < 2; ++which) {
            const float4* W1p = which ? s.W1ns4 : s.W1s4;
            const float4* W2p = which ? s.W2ns4 : s.W2s4;
            const float*  W3p = which ? s.W3ns  : s.W3s;
            const float*  b1p = which ? s.b1ns  : s.b1s;
            const float*  b2p = which ? s.b2ns  : s.b2s;
            const float   b3p = which ? b3nv    : b3v;

            float acc[8];
            // layer 1: 64 -> 128
            #pragma unroll
            for (int r = 0; r < 8; ++r) acc[r] = b1p[m];
            #pragma unroll 4
            for (int l4 = 0; l4 < 16; ++l4) {
                float4 w4 = W1p[l4 * 128 + m];
                #pragma unroll
                for (int r = 0; r < 8; ++r) {
                    float4 x4 = s.xws4[(g * 8 + r) * 16 + l4];
                    acc[r] = fmaf(x4.x, w4.x, acc[r]);
                    acc[r] = fmaf(x4.y, w4.y, acc[r]);
                    acc[r] = fmaf(x4.z, w4.z, acc[r]);
                    acc[r] = fmaf(x4.w, w4.w, acc[r]);
                }
            }
            #pragma unroll
            for (int r = 0; r < 8; ++r) s.H[(g * 8 + r) * 128 + m] = tanhf(acc[r]);
            __syncthreads();

            // layer 2: 128 -> 128
            #pragma unroll
            for (int r = 0; r < 8; ++r) acc[r] = b2p[m];
            {
                const float4* H4 = reinterpret_cast<const float4*>(s.H);
                #pragma unroll 4
                for (int l4 = 0; l4 < 32; ++l4) {
                    float4 w4 = W2p[l4 * 128 + m];
                    #pragma unroll
                    for (int r = 0; r < 8; ++r) {
                        float4 h4 = H4[(g * 8 + r) * 32 + l4];
                        acc[r] = fmaf(h4.x, w4.x, acc[r]);
                        acc[r] = fmaf(h4.y, w4.y, acc[r]);
                        acc[r] = fmaf(h4.z, w4.z, acc[r]);
                        acc[r] = fmaf(h4.w, w4.w, acc[r]);
                    }
                }
            }
            __syncthreads();   // all reads of H done before overwrite
            #pragma unroll
            for (int r = 0; r < 8; ++r) s.H[(g * 8 + r) * 128 + m] = tanhf(acc[r]);
            __syncthreads();

            // layer 3: 128 -> 1 (16 threads per row)
            {
                int r = tid >> 4, l16 = tid & 15;
                float p = 0.f;
                #pragma unroll
                for (int c = 0; c < 8; ++c)
                    p += s.H[r * 128 + l16 + c * 16] * W3p[l16 + c * 16];
                p += __shfl_down_sync(0xffffffffu, p, 8, 16);
                p += __shfl_down_sync(0xffffffffu, p, 4, 16);
                p += __shfl_down_sync(0xffffffffu, p, 2, 16);
                p += __shfl_down_sync(0xffffffffu, p, 1, 16);
                if (l16 == 0) {
                    float v = tanhf(p + b3p) * max_os;
                    if (which == 0) out_os[row0 + r] = v + s.ars[r];
                    else            g_xnn[row0 + r]  = v;
                }
            }
            __syncthreads();   // H reads done before next pass writes
        }
    }
}

// 8-way periodic stencil on x_nn + sigma fill.
// roll semantics: stencil[i,j,k] = mean of x_nn at ({i-1,i+1},j,{k-1,k+1})
// and (i,{j-1,j+1},{k-1,k+1}).
__global__ void stencil_kernel(const float* __restrict__ sigma_l,
                               float* __restrict__ out)
{
    int idx = blockIdx.x * blockDim.x + threadIdx.x;
    if (idx >= NROWS) return;
    int b = idx & 15;
    int k = (idx >> 4) & 31;
    int j = (idx >> 9) & 31;
    int i = (idx >> 14) & 31;
    int kp = (k + 1) & 31, km = (k + 31) & 31;
    int jp = (j + 1) & 31, jm = (j + 31) & 31;
    int ip = (i + 1) & 31, im = (i + 31) & 31;

    #define XNN(ii, jj, kk) g_xnn[(((((ii) << 5) | (jj)) << 5 | (kk)) << 4) | b]
    float sum = XNN(ip, j, kp) + XNN(ip, j, km)
              + XNN(im, j, kp) + XNN(im, j, km)
              + XNN(i, jp, kp) + XNN(i, jp, km)
              + XNN(i, jm, kp) + XNN(i, jm, km);
    #undef XNN

    out[idx] += 0.125f * sum;
    out[NROWS + idx] = expf(sigma_l[0]);
}

extern "C" void kernel_launch(void* const* d_in, const int* in_sizes, int n_in,
                              void* d_out, int out_size)
{
    const float* x_in     = (const float*)d_in[0];
    const float* weight   = (const float*)d_in[1];
    const float* ag       = (const float*)d_in[2];
    const float* W1       = (const float*)d_in[3];
    const float* b1       = (const float*)d_in[4];
    const float* W2       = (const float*)d_in[5];
    const float* b2       = (const float*)d_in[6];
    const float* W3       = (const float*)d_in[7];
    const float* b3       = (const float*)d_in[8];
    const float* W1n      = (const float*)d_in[9];
    const float* b1n      = (const float*)d_in[10];
    const float* W2n      = (const float*)d_in[11];
    const float* b2n      = (const float*)d_in[12];
    const float* W3n      = (const float*)d_in[13];
    const float* b3n      = (const float*)d_in[14];
    const float* max_os_l = (const float*)d_in[15];
    const float* sigma_l  = (const float*)d_in[16];
    float* out = (float*)d_out;

    cudaFuncSetAttribute(mlp_kernel, cudaFuncAttributeMaxDynamicSharedMemorySize,
                         (int)sizeof(Smem));

    mlp_kernel<<<148, THREADS, sizeof(Smem)>>>(
        x_in, weight, ag, W1, b1, W2, b2, W3, b3,
        W1n, b1n, W2n, b2n, W3n, b3n, max_os_l, out);

    stencil_kernel<<<(NROWS + 255) / 256, 256>>>(sigma_l, out);
}

// round 4
// speedup vs baseline: 2.6906x; 2.6906x over previous
#include <cuda_runtime.h>
#include <cuda_fp16.h>
#include <math.h>

#define NROWS   524288
#define NTILES  4096
#define TILE_M  128
#define THREADS 256
#define HALF_CTAS 74

// SMEM layout (byte offsets). Padded row strides: layer1 K=64 -> 144B rows,
// layer2 K=128 -> 272B rows (both = 4 words mod 32 banks: conflict-free ldmatrix).
#define W1HI 0
#define W1LO 18432
#define W2HI 36864
#define W2LO 71680
#define A1HI 106496
#define A1LO 124928
#define HHI  143360
#define HLO  178176
#define CTRL 212992
#define SMEM_BYTES (CTRL + 2560)

__device__ float g_xnn[NROWS];

struct Ctrl {
    float wt[64], ag[64];
    float b1s[128], b2s[128], W3s[128];
    float ars[128];
};

__device__ __forceinline__ unsigned smem_u32(const void* p) {
    unsigned a;
    asm("{ .reg .u64 t; cvta.to.shared.u64 t, %1; cvt.u32.u64 %0, t; }" : "=r"(a) : "l"(p));
    return a;
}
// tanh(x) = 1 - 2/(e^{2x}+1), via ex2.approx + rcp.approx (~1e-6 rel err)
__device__ __forceinline__ float tanh_acc(float x) {
    float e, r;
    asm("ex2.approx.f32 %0, %1;" : "=f"(e) : "f"(x * 2.8853900817779268f));
    asm("rcp.approx.f32 %0, %1;" : "=f"(r) : "f"(e + 1.0f));
    return fmaf(-2.0f, r, 1.0f);
}
__device__ __forceinline__ void ldm4(unsigned* d, unsigned addr) {
    asm volatile("ldmatrix.sync.aligned.m8n8.x4.shared.b16 {%0,%1,%2,%3}, [%4];"
        : "=r"(d[0]), "=r"(d[1]), "=r"(d[2]), "=r"(d[3]) : "r"(addr));
}
__device__ __forceinline__ void mma16816(float* c, const unsigned* a,
                                         unsigned b0, unsigned b1) {
    asm volatile("mma.sync.aligned.m16n8k16.row.col.f32.f16.f16.f32 "
        "{%0,%1,%2,%3}, {%4,%5,%6,%7}, {%8,%9}, {%0,%1,%2,%3};"
        : "+f"(c[0]), "+f"(c[1]), "+f"(c[2]), "+f"(c[3])
        : "r"(a[0]), "r"(a[1]), "r"(a[2]), "r"(a[3]), "r"(b0), "r"(b1));
}
__device__ __forceinline__ unsigned h16(float v) {
    return (unsigned)__half_as_ushort(__float2half_rn(v));
}

__global__ __launch_bounds__(THREADS, 1)
void mlp_mma_kernel(const float* __restrict__ x_in, const float* __restrict__ weight,
                    const float* __restrict__ ag,
                    const float* __restrict__ W1, const float* __restrict__ b1,
                    const float* __restrict__ W2, const float* __restrict__ b2,
                    const float* __restrict__ W3, const float* __restrict__ b3,
                    const float* __restrict__ W1n, const float* __restrict__ b1n,
                    const float* __restrict__ W2n, const float* __restrict__ b2n,
                    const float* __restrict__ W3n, const float* __restrict__ b3n,
                    const float* __restrict__ max_os_l,
                    float* __restrict__ out_os)
{
    extern __shared__ char tb[];
    const unsigned tb_u = smem_u32(tb);
    Ctrl* c = reinterpret_cast<Ctrl*>(tb + CTRL);

    const int tid = threadIdx.x;
    const int lane = tid & 31, warp = tid >> 5;
    const int li = lane & 7, ls = lane >> 3;
    const int qr = lane >> 2, qc = lane & 3;

    const int isnn = (blockIdx.x >= HALF_CTAS);
    const int cid  = blockIdx.x - (isnn ? HALF_CTAS : 0);

    const float* W1s = isnn ? W1n : W1;
    const float* W2s = isnn ? W2n : W2;
    const float* W3sel = isnn ? W3n : W3;
    const float* b1sel = isnn ? b1n : b1;
    const float* b2sel = isnn ? b2n : b2;
    const float  b3v = isnn ? b3n[0] : b3[0];
    const float  max_os = expf(max_os_l[0]);

    // ---- weights -> SMEM as f16 hi/lo, padded layouts ----
    for (int q = tid; q < 8192; q += THREADS) {       // W1 [128n][64k]
        int n = q >> 6, k = q & 63;
        float w = W1s[q];
        __half h = __float2half_rn(w);
        *(__half*)(tb + W1HI + n * 144 + k * 2) = h;
        *(__half*)(tb + W1LO + n * 144 + k * 2) = __float2half_rn(w - __half2float(h));
    }
    for (int q = tid; q < 16384; q += THREADS) {      // W2 [128n][128k]
        int n = q >> 7, k = q & 127;
        float w = W2s[q];
        __half h = __float2half_rn(w);
        *(__half*)(tb + W2HI + n * 272 + k * 2) = h;
        *(__half*)(tb + W2LO + n * 272 + k * 2) = __float2half_rn(w - __half2float(h));
    }
    if (tid < 128) {
        c->b1s[tid] = b1sel[tid];
        c->b2s[tid] = b2sel[tid];
        c->W3s[tid] = W3sel[tid];
    }
    if (tid < 64) { c->wt[tid] = weight[tid]; c->ag[tid] = ag[tid]; }
    __syncthreads();

    // ldmatrix lane address patterns
    const int a_row = warp * 16 + li + (ls & 1) * 8;
    const int a_koff = (ls >> 1) * 8;
    const unsigned aAddr1h = tb_u + A1HI + a_row * 144 + a_koff * 2;
    const unsigned aAddr1l = tb_u + A1LO + a_row * 144 + a_koff * 2;
    const unsigned aAddr2h = tb_u + HHI + a_row * 272 + a_koff * 2;
    const unsigned aAddr2l = tb_u + HLO + a_row * 272 + a_koff * 2;
    const unsigned bAddr1h = tb_u + W1HI + li * 144 + ls * 16;
    const unsigned bAddr1l = tb_u + W1LO + li * 144 + ls * 16;
    const unsigned bAddr2h = tb_u + W2HI + li * 272 + ls * 16;
    const unsigned bAddr2l = tb_u + W2LO + li * 272 + ls * 16;

    const int hrow0 = warp * 16 + qr;
    char* stH0 = tb + HHI + hrow0 * 272 + qc * 4;
    char* stH1 = stH0 + 8 * 272;
    char* stL0 = tb + HLO + hrow0 * 272 + qc * 4;
    char* stL1 = stL0 + 8 * 272;

    const float4* x4p = reinterpret_cast<const float4*>(x_in);

    for (int tile = cid; tile < NTILES; tile += HALF_CTAS) {
        const int row0 = tile * TILE_M;

        // ---- x tile: x_w -> A1 hi/lo f16 (padded rows) + AR dot ----
        for (int q = tid; q < 2048; q += THREADS) {
            int r = q >> 4, l4 = q & 15;
            float4 x4 = x4p[(size_t)(row0 + r) * 16 + l4];
            const float* wv = &c->wt[l4 * 4];
            const float* av = &c->ag[l4 * 4];
            float arp = x4.x * av[0] + x4.y * av[1] + x4.z * av[2] + x4.w * av[3];
            float v0 = x4.x * wv[0], v1 = x4.y * wv[1];
            float v2 = x4.z * wv[2], v3 = x4.w * wv[3];
            __half h0 = __float2half_rn(v0), h1 = __float2half_rn(v1);
            __half h2 = __float2half_rn(v2), h3 = __float2half_rn(v3);
            unsigned off = (unsigned)(r * 144 + l4 * 8);
            *(uint2*)(tb + A1HI + off) = make_uint2(
                (unsigned)__half_as_ushort(h0) | ((unsigned)__half_as_ushort(h1) << 16),
                (unsigned)__half_as_ushort(h2) | ((unsigned)__half_as_ushort(h3) << 16));
            *(uint2*)(tb + A1LO + off) = make_uint2(
                h16(v0 - __half2float(h0)) | (h16(v1 - __half2float(h1)) << 16),
                h16(v2 - __half2float(h2)) | (h16(v3 - __half2float(h3)) << 16));
            // AR reduce across the 16 threads covering this row
            arp += __shfl_down_sync(0xffffffffu, arp, 8, 16);
            arp += __shfl_down_sync(0xffffffffu, arp, 4, 16);
            arp += __shfl_down_sync(0xffffffffu, arp, 2, 16);
            arp += __shfl_down_sync(0xffffffffu, arp, 1, 16);
            if (l4 == 0) c->ars[r] = arp;
        }
        __syncthreads();

        // ---- layer 1: [16 rows x 64] @ W1^T -> C1[16 rows x 128] ----
        unsigned ah[4][4], al[4][4];
        #pragma unroll
        for (int kc = 0; kc < 4; ++kc) {
            ldm4(ah[kc], aAddr1h + kc * 32);
            ldm4(al[kc], aAddr1l + kc * 32);
        }
        float c1[16][4];
        #pragma unroll
        for (int n = 0; n < 16; ++n)
            c1[n][0] = c1[n][1] = c1[n][2] = c1[n][3] = 0.f;
        #pragma unroll
        for (int n = 0; n < 16; ++n) {
            unsigned bh[4], bl[4];
            #pragma unroll
            for (int kg = 0; kg < 2; ++kg) {
                ldm4(bh, bAddr1h + n * 1152 + kg * 64);
                ldm4(bl, bAddr1l + n * 1152 + kg * 64);
                #pragma unroll
                for (int s = 0; s < 2; ++s) {
                    int kc = kg * 2 + s;
                    mma16816(c1[n], ah[kc], bh[2 * s], bh[2 * s + 1]);
                    mma16816(c1[n], al[kc], bh[2 * s], bh[2 * s + 1]);
                    mma16816(c1[n], ah[kc], bl[2 * s], bl[2 * s + 1]);
                }
            }
        }

        // ---- epilogue 1: tanh(+b1) -> H hi/lo f16 (own rows only) ----
        #pragma unroll
        for (int n = 0; n < 16; ++n) {
            int col0 = n * 8 + qc * 2;
            float t00 = tanh_acc(c1[n][0] + c->b1s[col0]);
            float t01 = tanh_acc(c1[n][1] + c->b1s[col0 + 1]);
            float t10 = tanh_acc(c1[n][2] + c->b1s[col0]);
            float t11 = tanh_acc(c1[n][3] + c->b1s[col0 + 1]);
            __half h00 = __float2half_rn(t00), h01 = __float2half_rn(t01);
            __half h10 = __float2half_rn(t10), h11 = __float2half_rn(t11);
            *(unsigned*)(stH0 + n * 16) =
                (unsigned)__half_as_ushort(h00) | ((unsigned)__half_as_ushort(h01) << 16);
            *(unsigned*)(stH1 + n * 16) =
                (unsigned)__half_as_ushort(h10) | ((unsigned)__half_as_ushort(h11) << 16);
            *(unsigned*)(stL0 + n * 16) =
                h16(t00 - __half2float(h00)) | (h16(t01 - __half2float(h01)) << 16);
            *(unsigned*)(stL1 + n * 16) =
                h16(t10 - __half2float(h10)) | (h16(t11 - __half2float(h11)) << 16);
        }
        __syncwarp();

        // ---- layer 2: [16 rows x 128] @ W2^T -> C2[16 x 128] ----
        unsigned ah2[8][4], al2[8][4];
        #pragma unroll
        for (int kc = 0; kc < 8; ++kc) {
            ldm4(ah2[kc], aAddr2h + kc * 32);
            ldm4(al2[kc], aAddr2l + kc * 32);
        }
        float c2[16][4];
        #pragma unroll
        for (int n = 0; n < 16; ++n)
            c2[n][0] = c2[n][1] = c2[n][2] = c2[n][3] = 0.f;
        #pragma unroll
        for (int n = 0; n < 16; ++n) {
            unsigned bh[4], bl[4];
            #pragma unroll
            for (int kg = 0; kg < 4; ++kg) {
                ldm4(bh, bAddr2h + n * 2176 + kg * 64);
                ldm4(bl, bAddr2l + n * 2176 + kg * 64);
                mma16816(c2[n], ah2[2 * kg],     bh[0], bh[1]);
                mma16816(c2[n], al2[2 * kg],     bh[0], bh[1]);
                mma16816(c2[n], ah2[2 * kg],     bl[0], bl[1]);
                mma16816(c2[n], ah2[2 * kg + 1], bh[2], bh[3]);
                mma16816(c2[n], al2[2 * kg + 1], bh[2], bh[3]);
                mma16816(c2[n], ah2[2 * kg + 1], bl[2], bl[3]);
            }
        }

        // ---- epilogue 2: tanh(+b2) . W3, quad-reduce, final tanh ----
        float accR0 = 0.f, accR1 = 0.f;
        #pragma unroll
        for (int n = 0; n < 16; ++n) {
            int col0 = n * 8 + qc * 2;
            float w3a = c->W3s[col0], w3b = c->W3s[col0 + 1];
            float ba = c->b2s[col0], bb = c->b2s[col0 + 1];
            accR0 = fmaf(tanh_acc(c2[n][0] + ba), w3a, accR0);
            accR0 = fmaf(tanh_acc(c2[n][1] + bb), w3b, accR0);
            accR1 = fmaf(tanh_acc(c2[n][2] + ba), w3a, accR1);
            accR1 = fmaf(tanh_acc(c2[n][3] + bb), w3b, accR1);
        }
        accR0 += __shfl_xor_sync(0xffffffffu, accR0, 1);
        accR0 += __shfl_xor_sync(0xffffffffu, accR0, 2);
        accR1 += __shfl_xor_sync(0xffffffffu, accR1, 1);
        accR1 += __shfl_xor_sync(0xffffffffu, accR1, 2);
        if (qc == 0) {
            int r_local = warp * 16 + qr;
            int gr0 = row0 + r_local;
            float y0 = tanh_acc(accR0 + b3v) * max_os;
            float y1 = tanh_acc(accR1 + b3v) * max_os;
            if (!isnn) {
                out_os[gr0]     = y0 + c->ars[r_local];
                out_os[gr0 + 8] = y1 + c->ars[r_local + 8];
            } else {
                g_xnn[gr0]     = y0;
                g_xnn[gr0 + 8] = y1;
            }
        }
        __syncthreads();
    }
}

// 8-way periodic stencil on x_nn + sigma fill
__global__ void stencil_kernel(const float* __restrict__ sigma_l,
                               float* __restrict__ out)
{
    int idx = blockIdx.x * blockDim.x + threadIdx.x;
    if (idx >= NROWS) return;
    int b = idx & 15;
    int k = (idx >> 4) & 31;
    int j = (idx >> 9) & 31;
    int i = (idx >> 14) & 31;
    int kp = (k + 1) & 31, km = (k + 31) & 31;
    int jp = (j + 1) & 31, jm = (j + 31) & 31;
    int ip = (i + 1) & 31, im = (i + 31) & 31;

    #define XNN(ii, jj, kk) g_xnn[(((((ii) << 5) | (jj)) << 5 | (kk)) << 4) | b]
    float sum = XNN(ip, j, kp) + XNN(ip, j, km)
              + XNN(im, j, kp) + XNN(im, j, km)
              + XNN(i, jp, kp) + XNN(i, jp, km)
              + XNN(i, jm, kp) + XNN(i, jm, km);
    #undef XNN

    out[idx] += 0.125f * sum;
    out[NROWS + idx] = expf(sigma_l[0]);
}

extern "C" void kernel_launch(void* const* d_in, const int* in_sizes, int n_in,
                              void* d_out, int out_size)
{
    const float* x_in     = (const float*)d_in[0];
    const float* weight   = (const float*)d_in[1];
    const float* ag       = (const float*)d_in[2];
    const float* W1       = (const float*)d_in[3];
    const float* b1       = (const float*)d_in[4];
    const float* W2       = (const float*)d_in[5];
    const float* b2       = (const float*)d_in[6];
    const float* W3       = (const float*)d_in[7];
    const float* b3       = (const float*)d_in[8];
    const float* W1n      = (const float*)d_in[9];
    const float* b1n      = (const float*)d_in[10];
    const float* W2n      = (const float*)d_in[11];
    const float* b2n      = (const float*)d_in[12];
    const float* W3n      = (const float*)d_in[13];
    const float* b3n      = (const float*)d_in[14];
    const float* max_os_l = (const float*)d_in[15];
    const float* sigma_l  = (const float*)d_in[16];
    float* out = (float*)d_out;

    cudaFuncSetAttribute(mlp_mma_kernel, cudaFuncAttributeMaxDynamicSharedMemorySize,
                         SMEM_BYTES);

    mlp_mma_kernel<<<2 * HALF_CTAS, THREADS, SMEM_BYTES>>>(
        x_in, weight, ag, W1, b1, W2, b2, W3, b3,
        W1n, b1n, W2n, b2n, W3n, b3n, max_os_l, out);

    stencil_kernel<<<(NROWS + 255) / 256, 256>>>(sigma_l, out);
}